// round 11
// baseline (speedup 1.0000x reference)
#include <cuda_runtime.h>
#include <math.h>

#define LSEQ 262144
#define NMODE 64
#define TCH 64
#define NCHUNK (LSEQ / TCH)     // 4096
#define CB 16                   // chunks per GEMM block
#define GRID_G (NCHUNK / CB)    // 256

typedef unsigned long long u64;

// Per-mode scan constants
__device__ float g_wre[NMODE],  g_wim[NMODE];   // w = z^TCH
__device__ float g_w4re[NMODE], g_w4im[NMODE];  // w^4
// Packed tables (16B records, loaded as ulonglong2 = two ready f32x2 operands):
// g_Vpk[j][mp] = (Vr[2mp], Vr[2mp+1], Vi[2mp], Vi[2mp+1]),  V[j][m] = z_m^(63-j)
__device__ __align__(16) float4 g_Vpk[TCH * 32];
// g_Gpk[m][dp] = (Gr[m][2dp], Gr[m][2dp+1], Gin[m][2dp], Gin[m][2dp+1]),
//   G[m][d] = cf_m * z_m^(d+1), Gin = -Im(G)
__device__ __align__(16) float4 g_Gpk[NMODE * 32];
// padded pair table: g_ktab[t] = (Ktil[t-64], Ktil[t-63]), 0 outside [0,63]
__device__ __align__(16) u64 g_ktab[128];
// intermediates
__device__ __align__(16) float2 g_P[NMODE * NCHUNK];     // [mode][chunk]
__device__ __align__(16) float4 g_Ct4[NCHUNK * NMODE];   // [chunk][mode] = (Cr,Cr,Ci,Ci)

// ---- packed f32x2 helpers ----
__device__ __forceinline__ u64 pk2(float lo, float hi) {
    u64 r; asm("mov.b64 %0, {%1,%2};" : "=l"(r) : "f"(lo), "f"(hi)); return r;
}
__device__ __forceinline__ void upk2(u64 v, float& lo, float& hi) {
    asm("mov.b64 {%0,%1}, %2;" : "=f"(lo), "=f"(hi) : "l"(v));
}
__device__ __forceinline__ u64 fma2(u64 a, u64 b, u64 c) {
    u64 d; asm("fma.rn.f32x2 %0, %1, %2, %3;" : "=l"(d) : "l"(a), "l"(b), "l"(c)); return d;
}

// Float-only setup: scan constants + packed V/G tables + Ktilde pair table.
__global__ void setup_kernel(const float* __restrict__ A_re,
                             const float* __restrict__ A_im,
                             const float* __restrict__ C,
                             const float* __restrict__ log_step) {
    __shared__ float sRe[NMODE * 65], sIm[NMODE * 65];   // pitch 65
    __shared__ float sCfr[NMODE], sKt[TCH];
    int n = threadIdx.x;   // 64 threads = one mode each
    float dt  = expf(log_step[0]);
    float ar  = A_re[n], ai = A_im[n];
    float dre = dt * ar, dim = dt * ai;
    float em  = expf(dre);
    float zr  = em * cosf(dim), zi = em * sinf(dim);
    float nr = zr - 1.f, ni = zi;
    float inv = 1.f / (ar * ar + ai * ai);
    float tre = (nr * ar + ni * ai) * inv;
    float tim = (ni * ar - nr * ai) * inv;
    float cr = C[2 * n], ci = C[2 * n + 1];
    float cfr = cr * tre - ci * tim;
    float cfi = cr * tim + ci * tre;
    // w = z^64, w^4
    float p2r = zr * zr - zi * zi,          p2i = 2.f * zr * zi;
    float p4r = p2r * p2r - p2i * p2i,      p4i = 2.f * p2r * p2i;
    float p8r  = p4r * p4r - p4i * p4i,     p8i  = 2.f * p4r * p4i;
    float p16r = p8r * p8r - p8i * p8i,     p16i = 2.f * p8r * p8i;
    float p32r = p16r * p16r - p16i * p16i, p32i = 2.f * p16r * p16i;
    float wr   = p32r * p32r - p32i * p32i, wi   = 2.f * p32r * p32i;
    g_wre[n] = wr; g_wim[n] = wi;
    float w2r = wr * wr - wi * wi,     w2i = 2.f * wr * wi;
    g_w4re[n] = w2r * w2r - w2i * w2i;
    g_w4im[n] = 2.f * w2r * w2i;
    sCfr[n] = cfr;
    // --- V staging: sRe[j*65+n] = Re z^(63-j) ---
    {
        float pr = 1.f, pi = 0.f;
        for (int k = 0; k < TCH; k++) {
            int j = TCH - 1 - k;
            sRe[j * 65 + n] = pr;  sIm[j * 65 + n] = pi;
            float t1 = pr * zr - pi * zi;
            pi = pr * zi + pi * zr; pr = t1;
        }
    }
    __syncthreads();
    for (int mp = 0; mp < 32; mp++) {
        g_Vpk[n * 32 + mp] = make_float4(sRe[n * 65 + 2 * mp], sRe[n * 65 + 2 * mp + 1],
                                         sIm[n * 65 + 2 * mp], sIm[n * 65 + 2 * mp + 1]);
    }
    __syncthreads();
    // --- G staging ---
    {
        float gr = cfr, gi = cfi;
        for (int d = 0; d < TCH; d++) {
            float t1 = gr * zr - gi * zi;
            gi = gr * zi + gi * zr; gr = t1;
            sRe[n * 65 + d] = gr;  sIm[n * 65 + d] = gi;
        }
    }
    __syncthreads();
    for (int dp = 0; dp < 32; dp++) {
        g_Gpk[n * 32 + dp] = make_float4(sRe[n * 65 + 2 * dp], sRe[n * 65 + 2 * dp + 1],
                                         -sIm[n * 65 + 2 * dp], -sIm[n * 65 + 2 * dp + 1]);
    }
    // Ktilde
    {
        float acc = 0.f;
        if (n == 0) { for (int m = 0; m < NMODE; m++) acc += sCfr[m]; }
        else        { for (int m = 0; m < NMODE; m++) acc += sRe[m * 65 + n - 1]; }
        sKt[n] = acc;
    }
    __syncthreads();
    for (int t = n; t < 128; t += 64) {
        int li = t - 64, hi = t - 63;
        float lo = (li >= 0 && li < TCH) ? sKt[li] : 0.f;
        float hh = (hi >= 0 && hi < TCH) ? sKt[hi] : 0.f;
        g_ktab[t] = pk2(lo, hh);
    }
}

// Phase 1: partials GEMM  P[m][c] = sum_j V[j][m]*u[cT+j].
// Warp = 2 chunks x 32 mode-pairs (lane=mp). u via broadcast LDG.128,
// V via per-lane coalesced LDG.128 (ulonglong2: vr-pair, vi-pair). No input smem.
__global__ __launch_bounds__(256) void pgemm_kernel(const float* __restrict__ u) {
    __shared__ __align__(16) float2 sPst[NMODE * 17];     // staging, pitch 17
    int tid = threadIdx.x;
    int cb0 = blockIdx.x * CB;
    int lane = tid & 31, c0 = (tid >> 5) * 2;
    const float4* up0 = (const float4*)&u[(cb0 + c0) * TCH];
    const float4* up1 = up0 + (TCH / 4);
    u64 ar0 = 0, ai0 = 0, ar1 = 0, ai1 = 0;
#pragma unroll 4
    for (int jq = 0; jq < 16; jq++) {
        float4 x0 = __ldg(&up0[jq]);
        float4 x1 = __ldg(&up1[jq]);
        const ulonglong2* vp = (const ulonglong2*)&g_Vpk[(4 * jq) * 32 + lane];
        ulonglong2 v0 = __ldg(vp);
        ulonglong2 v1 = __ldg(vp + 32);
        ulonglong2 v2 = __ldg(vp + 64);
        ulonglong2 v3 = __ldg(vp + 96);
        u64 s;
        s = pk2(x0.x, x0.x); ar0 = fma2(v0.x, s, ar0); ai0 = fma2(v0.y, s, ai0);
        s = pk2(x0.y, x0.y); ar0 = fma2(v1.x, s, ar0); ai0 = fma2(v1.y, s, ai0);
        s = pk2(x0.z, x0.z); ar0 = fma2(v2.x, s, ar0); ai0 = fma2(v2.y, s, ai0);
        s = pk2(x0.w, x0.w); ar0 = fma2(v3.x, s, ar0); ai0 = fma2(v3.y, s, ai0);
        s = pk2(x1.x, x1.x); ar1 = fma2(v0.x, s, ar1); ai1 = fma2(v0.y, s, ai1);
        s = pk2(x1.y, x1.y); ar1 = fma2(v1.x, s, ar1); ai1 = fma2(v1.y, s, ai1);
        s = pk2(x1.z, x1.z); ar1 = fma2(v2.x, s, ar1); ai1 = fma2(v2.y, s, ai1);
        s = pk2(x1.w, x1.w); ar1 = fma2(v3.x, s, ar1); ai1 = fma2(v3.y, s, ai1);
    }
    float r0, r1, i0, i1;
    upk2(ar0, r0, r1); upk2(ai0, i0, i1);
    sPst[(2 * lane) * 17 + c0]     = make_float2(r0, i0);
    sPst[(2 * lane + 1) * 17 + c0] = make_float2(r1, i1);
    upk2(ar1, r0, r1); upk2(ai1, i0, i1);
    sPst[(2 * lane) * 17 + c0 + 1]     = make_float2(r0, i0);
    sPst[(2 * lane + 1) * 17 + c0 + 1] = make_float2(r1, i1);
    __syncthreads();
    // coalesced writeout: 64 rows x 16 float2
    int row = tid >> 2, cq = (tid & 3) * 4;
    float2 a = sPst[row * 17 + cq],     b = sPst[row * 17 + cq + 1];
    float2 c = sPst[row * 17 + cq + 2], d = sPst[row * 17 + cq + 3];
    float2* gp = &g_P[row * NCHUNK + cb0 + cq];
    *(float4*)&gp[0] = make_float4(a.x, a.y, b.x, b.y);
    *(float4*)&gp[2] = make_float4(c.x, c.y, d.x, d.y);
}

// Phase 2: per-mode scan; fold 4 (Horner w), scan W=w^4.
// Emits pre-splatted transposed carries g_Ct4[chunk][mode] = (Cr,Cr,Ci,Ci).
__global__ __launch_bounds__(1024) void scan_kernel() {
    __shared__ float sre[1024], sim_[1024];
    int mode = blockIdx.x, t = threadIdx.x;
    float wr = g_wre[mode], wi = g_wim[mode];
    const float2* P = &g_P[mode * NCHUNK];
    float4 pa = *(const float4*)&P[4 * t];
    float4 pb = *(const float4*)&P[4 * t + 2];
    float p0r = pa.x, p0i = pa.y, p1r = pa.z, p1i = pa.w;
    float p2r = pb.x, p2i = pb.y, p3r = pb.z, p3i = pb.w;
    float vr = p0r, vi = p0i, nr, ni;
    nr = fmaf(wr, vr, fmaf(-wi, vi, p1r));
    ni = fmaf(wi, vr, fmaf( wr, vi, p1i)); vr = nr; vi = ni;
    nr = fmaf(wr, vr, fmaf(-wi, vi, p2r));
    ni = fmaf(wi, vr, fmaf( wr, vi, p2i)); vr = nr; vi = ni;
    nr = fmaf(wr, vr, fmaf(-wi, vi, p3r));
    ni = fmaf(wi, vr, fmaf( wr, vi, p3i)); vr = nr; vi = ni;
    sre[t] = vr; sim_[t] = vi;
    float cwr = g_w4re[mode], cwi = g_w4im[mode];
    __syncthreads();
    for (int k = 1; k < 1024; k <<= 1) {
        float ore = 0.f, oim = 0.f;
        if (t >= k) { ore = sre[t - k]; oim = sim_[t - k]; }
        __syncthreads();
        vr += cwr * ore - cwi * oim;
        vi += cwr * oim + cwi * ore;
        sre[t] = vr; sim_[t] = vi;
        float nwr = cwr * cwr - cwi * cwi;
        cwi = 2.f * cwr * cwi; cwr = nwr;
        __syncthreads();
    }
    float e0r = 0.f, e0i = 0.f;
    if (t > 0) { e0r = sre[t - 1]; e0i = sim_[t - 1]; }
    float e1r = fmaf(wr, e0r, fmaf(-wi, e0i, p0r));
    float e1i = fmaf(wi, e0r, fmaf( wr, e0i, p0i));
    float e2r = fmaf(wr, e1r, fmaf(-wi, e1i, p1r));
    float e2i = fmaf(wi, e1r, fmaf( wr, e1i, p1i));
    float e3r = fmaf(wr, e2r, fmaf(-wi, e2i, p2r));
    float e3i = fmaf(wi, e2r, fmaf( wr, e2i, p2i));
    int cbase = 4 * t;
    g_Ct4[(cbase + 0) * NMODE + mode] = make_float4(e0r, e0r, e0i, e0i);
    g_Ct4[(cbase + 1) * NMODE + mode] = make_float4(e1r, e1r, e1i, e1i);
    g_Ct4[(cbase + 2) * NMODE + mode] = make_float4(e2r, e2r, e2i, e2i);
    g_Ct4[(cbase + 3) * NMODE + mode] = make_float4(e3r, e3r, e3i, e3i);
}

// Phase 3: y = D*u + triangular-Toeplitz(Ktil) x u + G x carry.
// Warp = 2 chunks x 32 delta-pairs (lane=dp). K from tiny smem table;
// u/C via broadcast LDG, G via per-lane coalesced LDG — near-zero LDS.
__global__ __launch_bounds__(256) void ygemm_kernel(const float* __restrict__ u,
                                                    const float* __restrict__ D,
                                                    float* __restrict__ y) {
    __shared__ __align__(16) u64 sK[128];
    int tid = threadIdx.x;
    int cb0 = blockIdx.x * CB;
    if (tid < 128) sK[tid] = g_ktab[tid];
    __syncthreads();

    int lane = tid & 31;
    int c0 = cb0 + (tid >> 5) * 2;    // global chunk
    const float4* up0 = (const float4*)&u[c0 * TCH];
    const float4* up1 = up0 + (TCH / 4);
    const u64* kb = &sK[64 + 2 * lane];
    u64 a0 = 0, a1 = 0;
#pragma unroll 4
    for (int jq = 0; jq < 16; jq++) {
        float4 x0 = __ldg(&up0[jq]);
        float4 x1 = __ldg(&up1[jq]);
        int j0 = 4 * jq;
        u64 k0 = kb[-j0], k1 = kb[-j0 - 1], k2 = kb[-j0 - 2], k3 = kb[-j0 - 3];
        u64 s;
        s = pk2(x0.x, x0.x); a0 = fma2(k0, s, a0);
        s = pk2(x0.y, x0.y); a0 = fma2(k1, s, a0);
        s = pk2(x0.z, x0.z); a0 = fma2(k2, s, a0);
        s = pk2(x0.w, x0.w); a0 = fma2(k3, s, a0);
        s = pk2(x1.x, x1.x); a1 = fma2(k0, s, a1);
        s = pk2(x1.y, x1.y); a1 = fma2(k1, s, a1);
        s = pk2(x1.z, x1.z); a1 = fma2(k2, s, a1);
        s = pk2(x1.w, x1.w); a1 = fma2(k3, s, a1);
    }
    // correction: a += Gr*Cr + Gin*Ci  (all operands pre-packed, zero movs)
    const ulonglong2* Gp  = (const ulonglong2*)&g_Gpk[lane];
    const ulonglong2* cA  = (const ulonglong2*)&g_Ct4[c0 * NMODE];
    const ulonglong2* cB  = cA + NMODE;
#pragma unroll 8
    for (int m = 0; m < NMODE; m++) {
        ulonglong2 gv = __ldg(&Gp[m * 32]);
        ulonglong2 ca = __ldg(&cA[m]);
        ulonglong2 cb_ = __ldg(&cB[m]);
        a0 = fma2(gv.x, ca.x,  a0);  a0 = fma2(gv.y, ca.y,  a0);
        a1 = fma2(gv.x, cb_.x, a1);  a1 = fma2(gv.y, cb_.y, a1);
    }
    float Dv = __ldg(D);
    float o0, o1;
    {
        int idx = c0 * TCH + 2 * lane;
        float2 uv = *(const float2*)&u[idx];
        upk2(a0, o0, o1);
        *(float2*)&y[idx] = make_float2(fmaf(Dv, uv.x, o0), fmaf(Dv, uv.y, o1));
    }
    {
        int idx = (c0 + 1) * TCH + 2 * lane;
        float2 uv = *(const float2*)&u[idx];
        upk2(a1, o0, o1);
        *(float2*)&y[idx] = make_float2(fmaf(Dv, uv.x, o0), fmaf(Dv, uv.y, o1));
    }
}

extern "C" void kernel_launch(void* const* d_in, const int* in_sizes, int n_in,
                              void* d_out, int out_size) {
    const float* u        = (const float*)d_in[0];
    const float* A_re     = (const float*)d_in[1];
    const float* A_im     = (const float*)d_in[2];
    const float* C        = (const float*)d_in[3];
    const float* D        = (const float*)d_in[4];
    const float* log_step = (const float*)d_in[5];
    float* y = (float*)d_out;

    setup_kernel<<<1, NMODE>>>(A_re, A_im, C, log_step);
    pgemm_kernel<<<GRID_G, 256>>>(u);
    scan_kernel<<<NMODE, 1024>>>();
    ygemm_kernel<<<GRID_G, 256>>>(u, D, y);
}

// round 12
// speedup vs baseline: 2.2394x; 2.2394x over previous
#include <cuda_runtime.h>
#include <math.h>

#define LSEQ 262144
#define NMODE 64
#define TCH 128
#define NCHUNK (LSEQ / TCH)   // 2048
#define WPB 8
#define BTH 256
#define NBLK (NCHUNK / WPB)   // 256 blocks

typedef unsigned long long u64;

// intermediates [mode][chunk]
__device__ __align__(16) float2 g_P[NMODE * NCHUNK];
__device__ __align__(16) float2 g_C[NMODE * NCHUNK];
// grid barrier counters (monotonic across graph replays)
__device__ u64 g_bar1 = 0, g_bar2 = 0;

// ---- packed f32x2 helpers ----
__device__ __forceinline__ u64 pk2(float lo, float hi) {
    u64 r; asm("mov.b64 %0, {%1,%2};" : "=l"(r) : "f"(lo), "f"(hi)); return r;
}
__device__ __forceinline__ void upk2(u64 v, float& lo, float& hi) {
    asm("mov.b64 {%0,%1}, %2;" : "=f"(lo), "=f"(hi) : "l"(v));
}
__device__ __forceinline__ u64 fma2(u64 a, u64 b, u64 c) {
    u64 d; asm("fma.rn.f32x2 %0, %1, %2, %3;" : "=l"(d) : "l"(a), "l"(b), "l"(c)); return d;
}
__device__ __forceinline__ u64 mul2(u64 a, u64 b) {
    u64 d; asm("mul.rn.f32x2 %0, %1, %2;" : "=l"(d) : "l"(a), "l"(b)); return d;
}

// Replay-safe grid barrier: every launch adds exactly NBLK arrivals, so the
// counter is ≡ 0 (mod NBLK) at launch start; target derives from own arrival.
__device__ __forceinline__ void grid_barrier(u64* ctr) {
    __syncthreads();
    if (threadIdx.x == 0) {
        __threadfence();
        u64 old = atomicAdd(ctr, 1ULL);
        u64 target = (old / NBLK + 1) * (u64)NBLK;
        while (*(volatile u64*)ctr < target) __nanosleep(32);
        __threadfence();
    }
    __syncthreads();
}

__global__ __launch_bounds__(BTH) void fused_kernel(
    const float* __restrict__ u, const float* __restrict__ A_re,
    const float* __restrict__ A_im, const float* __restrict__ Cin,
    const float* __restrict__ D, const float* __restrict__ log_step,
    float* __restrict__ y)
{
    __shared__ __align__(16) float su[WPB * TCH];       // 4KB, lives A->C
    __shared__ __align__(16) float2 sP[NMODE][WPB];     // 4KB (partials, then carries)
    __shared__ __align__(16) float red[WPB][32 * 34];   // ~34.8KB transpose-reduce
    __shared__ float sre[BTH], sim_[BTH];               // 2KB scan

    int tid = threadIdx.x, warp = tid >> 5, lane = tid & 31;
    int blk = blockIdx.x;
    int base = blk * (WPB * TCH);

    // ---- per-lane constants for modes (lane, lane+32), registers persist ----
    float dt = expf(__ldg(log_step));
    float zr0, zi0, zr1, zi1, cfr0, cfi0, cfr1, cfi1;
    {
        int m = lane;
        float ar = __ldg(&A_re[m]), ai = __ldg(&A_im[m]);
        float e = expf(dt * ar);
        zr0 = e * cosf(dt * ai); zi0 = e * sinf(dt * ai);
        float nr = zr0 - 1.f, ni = zi0;
        float inv = 1.f / (ar * ar + ai * ai);
        float tre = (nr * ar + ni * ai) * inv, tim = (ni * ar - nr * ai) * inv;
        float cr = __ldg(&Cin[2 * m]), ci = __ldg(&Cin[2 * m + 1]);
        cfr0 = cr * tre - ci * tim; cfi0 = cr * tim + ci * tre;
    }
    {
        int m = lane + 32;
        float ar = __ldg(&A_re[m]), ai = __ldg(&A_im[m]);
        float e = expf(dt * ar);
        zr1 = e * cosf(dt * ai); zi1 = e * sinf(dt * ai);
        float nr = zr1 - 1.f, ni = zi1;
        float inv = 1.f / (ar * ar + ai * ai);
        float tre = (nr * ar + ni * ai) * inv, tim = (ni * ar - nr * ai) * inv;
        float cr = __ldg(&Cin[2 * m]), ci = __ldg(&Cin[2 * m + 1]);
        cfr1 = cr * tre - ci * tim; cfi1 = cr * tim + ci * tre;
    }
    u64 Zr = pk2(zr0, zr1), Zi = pk2(zi0, zi1), nZi = pk2(-zi0, -zi1);
    float z2r0 = zr0 * zr0 - zi0 * zi0, z2i0 = 2.f * zr0 * zi0;
    float z2r1 = zr1 * zr1 - zi1 * zi1, z2i1 = 2.f * zr1 * zi1;
    u64 Z2r = pk2(z2r0, z2r1), Z2i = pk2(z2i0, z2i1), nZ2i = pk2(-z2i0, -z2i1);
    float z4r0 = z2r0 * z2r0 - z2i0 * z2i0, z4i0 = 2.f * z2r0 * z2i0;
    float z4r1 = z2r1 * z2r1 - z2i1 * z2i1, z4i1 = 2.f * z2r1 * z2i1;
    u64 Z4r = pk2(z4r0, z4r1), Z4i = pk2(z4i0, z4i1), nZ4i = pk2(-z4i0, -z4i1);
    u64 F = pk2(cfr0, cfr1), nFi = pk2(-cfi0, -cfi1);

    // ================= Phase A: chunk partials (zero-init recurrence) ========
    ((float4*)su)[tid] = ((const float4*)(u + base))[tid];
    __syncthreads();
    {
        u64 sr = 0, si = 0;
        const float4* uw = (const float4*)&su[warp * TCH];
#pragma unroll
        for (int i = 0; i < TCH / 4; i++) {
            float4 uu = uw[i];
            u64 u1p = pk2(uu.x, uu.x), u2p = pk2(uu.y, uu.y);
            u64 u3p = pk2(uu.z, uu.z), u4p = pk2(uu.w, uu.w);
            u64 t1r = fma2(Zr, u1p, u2p), t1i = mul2(Zi, u1p);
            u64 t2r = fma2(Zr, u3p, u4p), t2i = mul2(Zi, u3p);
            u64 br = fma2(Z2r, t1r, fma2(nZ2i, t1i, t2r));
            u64 bi = fma2(Z2i, t1r, fma2(Z2r, t1i, t2i));
            u64 nr = fma2(Z4r, sr, fma2(nZ4i, si, br));
            u64 ni = fma2(Z4i, sr, fma2(Z4r, si, bi));
            sr = nr; si = ni;
        }
        float a, b, c, d;
        upk2(sr, a, b); upk2(si, c, d);
        sP[lane][warp]      = make_float2(a, c);
        sP[lane + 32][warp] = make_float2(b, d);
    }
    __syncthreads();
    {
        int row = tid >> 2, col = (tid & 3) * 2, c0 = blk * WPB;
        *(float4*)&g_P[row * NCHUNK + c0 + col] = *(const float4*)&sP[row][col];
    }
    grid_barrier(&g_bar1);

    // ================= Phase B: per-mode scan (blocks 0..63) =================
    if (blk < NMODE) {
        int mode = blk;
        float ar = __ldg(&A_re[mode]), ai = __ldg(&A_im[mode]);
        float e = expf(dt * ar);
        float wr = e * cosf(dt * ai), wi = e * sinf(dt * ai);
#pragma unroll
        for (int k = 0; k < 7; k++) { float t1 = wr * wr - wi * wi; wi = 2.f * wr * wi; wr = t1; }  // z^128
        float Wr = wr, Wi = wi;
#pragma unroll
        for (int k = 0; k < 3; k++) { float t1 = Wr * Wr - Wi * Wi; Wi = 2.f * Wr * Wi; Wr = t1; }  // w^8
        int t = tid;
        float2 p[8];
        const float2* P = &g_P[mode * NCHUNK + 8 * t];
#pragma unroll
        for (int q = 0; q < 4; q++) {
            float4 a = *(const float4*)&P[2 * q];
            p[2 * q]     = make_float2(a.x, a.y);
            p[2 * q + 1] = make_float2(a.z, a.w);
        }
        float vr = p[0].x, vi = p[0].y;
#pragma unroll
        for (int j = 1; j < 8; j++) {
            float nr2 = fmaf(wr, vr, fmaf(-wi, vi, p[j].x));
            float ni2 = fmaf(wi, vr, fmaf( wr, vi, p[j].y));
            vr = nr2; vi = ni2;
        }
        sre[t] = vr; sim_[t] = vi;
        float cwr = Wr, cwi = Wi;
        __syncthreads();
        for (int k = 1; k < BTH; k <<= 1) {
            float ore = 0.f, oim = 0.f;
            if (t >= k) { ore = sre[t - k]; oim = sim_[t - k]; }
            __syncthreads();
            vr += cwr * ore - cwi * oim;
            vi += cwr * oim + cwi * ore;
            sre[t] = vr; sim_[t] = vi;
            float nwr = cwr * cwr - cwi * cwi;
            cwi = 2.f * cwr * cwi; cwr = nwr;
            __syncthreads();
        }
        float er = 0.f, ei = 0.f;
        if (t > 0) { er = sre[t - 1]; ei = sim_[t - 1]; }
        float2 ec[8];
        ec[0] = make_float2(er, ei);
#pragma unroll
        for (int j = 1; j < 8; j++) {
            float nr2 = fmaf(wr, er, fmaf(-wi, ei, p[j - 1].x));
            float ni2 = fmaf(wi, er, fmaf( wr, ei, p[j - 1].y));
            er = nr2; ei = ni2;
            ec[j] = make_float2(er, ei);
        }
        float2* Cp = &g_C[mode * NCHUNK + 8 * t];
#pragma unroll
        for (int q = 0; q < 4; q++)
            *(float4*)&Cp[2 * q] = make_float4(ec[2 * q].x, ec[2 * q].y,
                                               ec[2 * q + 1].x, ec[2 * q + 1].y);
    }
    grid_barrier(&g_bar2);

    // ================= Phase C: carry-seeded output recurrence ===============
    {
        int row = tid >> 2, col = (tid & 3) * 2, c0 = blk * WPB;
        *(float4*)&sP[row][col] = *(const float4*)&g_C[row * NCHUNK + c0 + col];
    }
    __syncthreads();
    {
        float2 cA = sP[lane][warp], cB = sP[lane + 32][warp];
        u64 sr = pk2(cA.x, cB.x), si = pk2(cA.y, cB.y);
        float Dv = __ldg(D);
        float* rw = &red[warp][0];
        int gbase = base + warp * TCH;
#pragma unroll
        for (int tile = 0; tile < TCH / 32; tile++) {
#pragma unroll
            for (int i = 0; i < 32; i += 2) {
                float2 uu = *(const float2*)&su[warp * TCH + tile * 32 + i];
                u64 u1 = pk2(uu.x, uu.x), u2 = pk2(uu.y, uu.y);
                u64 tr = fma2(Zr, sr, fma2(nZi, si, u1));
                u64 ti = fma2(Zi, sr, mul2(Zr, si));
                u64 br = fma2(Zr, u1, u2), bi = mul2(Zi, u1);
                u64 vr = fma2(Z2r, sr, fma2(nZ2i, si, br));
                u64 vi = fma2(Z2i, sr, fma2(Z2r, si, bi));
                sr = vr; si = vi;
                u64 c1 = fma2(F, tr, mul2(nFi, ti));
                u64 c2 = fma2(F, vr, mul2(nFi, vi));
                float a0, a1, b0, b1;
                upk2(c1, a0, a1); upk2(c2, b0, b1);
                *(float2*)&rw[lane * 34 + i] = make_float2(a0 + a1, b0 + b1);
            }
            __syncwarp();
            float acc0 = 0.f, acc1 = 0.f, acc2 = 0.f, acc3 = 0.f;
#pragma unroll
            for (int l = 0; l < 32; l += 4) {
                acc0 += rw[(l + 0) * 34 + lane];
                acc1 += rw[(l + 1) * 34 + lane];
                acc2 += rw[(l + 2) * 34 + lane];
                acc3 += rw[(l + 3) * 34 + lane];
            }
            float uv = su[warp * TCH + tile * 32 + lane];
            y[gbase + tile * 32 + lane] = fmaf(Dv, uv, (acc0 + acc1) + (acc2 + acc3));
            __syncwarp();
        }
    }
}

extern "C" void kernel_launch(void* const* d_in, const int* in_sizes, int n_in,
                              void* d_out, int out_size) {
    const float* u        = (const float*)d_in[0];
    const float* A_re     = (const float*)d_in[1];
    const float* A_im     = (const float*)d_in[2];
    const float* C        = (const float*)d_in[3];
    const float* D        = (const float*)d_in[4];
    const float* log_step = (const float*)d_in[5];
    float* y = (float*)d_out;

    // Force max shared-memory carveout so >=2 blocks/SM are guaranteed
    // resident (grid barrier liveness: 256 blocks on 148 SMs).
    static int once = 0;
    if (!once) {
        cudaFuncSetAttribute(fused_kernel,
                             cudaFuncAttributePreferredSharedMemoryCarveout, 100);
        once = 1;
    }
    fused_kernel<<<NBLK, BTH>>>(u, A_re, A_im, C, D, log_step, y);
}